// round 1
// baseline (speedup 1.0000x reference)
#include <cuda_runtime.h>

// Problem dims (fixed by the dataset)
#define S_ 4
#define B_ 512
#define D_ 256
#define H_ 1024
#define T_ 50
#define M_ (S_*B_)          // 2048 rows
#define PRED (M_*T_*D_)     // pred_y element count

// Scratch: __device__ globals (no allocation allowed)
__device__ float g_H1[M_*H_];
__device__ float g_H2[M_*H_];
__device__ float g_K1[M_*D_];
__device__ float g_K2[M_*D_];
__device__ float g_K3[M_*D_];
__device__ float g_Y [M_*D_];

enum { BUF_Y, BUF_H1, BUF_H2, BUF_K1, BUF_K2, BUF_K3 };

__device__ __forceinline__ float* gbuf(int id) {
    switch (id) {
        case BUF_Y:  return g_Y;
        case BUF_H1: return g_H1;
        case BUF_H2: return g_H2;
        case BUF_K1: return g_K1;
        case BUF_K2: return g_K2;
        default:     return g_K3;
    }
}

// tanh(x) = 1 - 2/(e^{2x}+1); exact at +/-inf, abs err ~1e-7 — cheap (MUFU.EX2 + RCP)
__device__ __forceinline__ float fast_tanh(float x) {
    float t = __expf(2.0f * x);
    return 1.0f - 2.0f / (t + 1.0f);
}

// Fused GEMM: C[M,N] = epi(A'[M,K] @ W[K,N] + bias)
//   PRO==0: A' = buf(AID)
//   PRO==1: A' = buf(AID) + acoef*dt * buf(KID)        (RK4 probe state, fused)
//   EPI==0: out = tanh(.) -> buf(OID)
//   EPI==1: out = .       -> buf(OID)
//   EPI==2: k4 = .; y' = Y + dt/6*(K1+2K2+2K3+k4); Y=y'; traj[:,step+1,:]=y'
template<int BM,int BN,int BK,int TM,int TN,int K,int N,
         int AID,int KID,int OID,int PRO,int EPI>
__global__ void __launch_bounds__(256)
gemm_k(const float* __restrict__ W, const float* __restrict__ bias,
       float* __restrict__ dout, const float* __restrict__ tarr,
       int step, float acoef)
{
    constexpr int NT = 256;
    __shared__ float As[BK][BM];
    __shared__ float Bs[BK][BN];

    const float* __restrict__ A   = gbuf(AID);
    const float* __restrict__ Kin = gbuf(KID);

    float dt = 0.0f;
    if (PRO == 1 || EPI == 2) dt = tarr[step + 1] - tarr[step];
    const float alpha = (PRO == 1) ? acoef * dt : 0.0f;

    const int bm  = blockIdx.y * BM;
    const int bn  = blockIdx.x * BN;
    const int tid = threadIdx.x;
    const int tx  = tid % (BN / TN);
    const int ty  = tid / (BN / TN);

    float acc[TM][TN];
    #pragma unroll
    for (int i = 0; i < TM; i++)
        #pragma unroll
        for (int j = 0; j < TN; j++) acc[i][j] = 0.0f;

    constexpr int AV = (BM * BK) / (NT * 4);   // float4 A loads per thread
    constexpr int BV = (BK * BN) / (NT * 4);   // float4 B loads per thread

    for (int k0 = 0; k0 < K; k0 += BK) {
        #pragma unroll
        for (int l = 0; l < AV; l++) {
            int idx = tid + l * NT;
            int ar  = idx / (BK / 4);
            int ac  = (idx % (BK / 4)) * 4;
            float4 v = *(const float4*)(A + (size_t)(bm + ar) * K + k0 + ac);
            if (PRO == 1) {
                float4 w = *(const float4*)(Kin + (size_t)(bm + ar) * K + k0 + ac);
                v.x = fmaf(alpha, w.x, v.x); v.y = fmaf(alpha, w.y, v.y);
                v.z = fmaf(alpha, w.z, v.z); v.w = fmaf(alpha, w.w, v.w);
            }
            As[ac + 0][ar] = v.x; As[ac + 1][ar] = v.y;
            As[ac + 2][ar] = v.z; As[ac + 3][ar] = v.w;
        }
        #pragma unroll
        for (int l = 0; l < BV; l++) {
            int idx = tid + l * NT;
            int br  = idx / (BN / 4);
            int bc  = (idx % (BN / 4)) * 4;
            *(float4*)&Bs[br][bc] =
                *(const float4*)(W + (size_t)(k0 + br) * N + bn + bc);
        }
        __syncthreads();

        #pragma unroll
        for (int kk = 0; kk < BK; kk++) {
            float ar_[TM], br_[TN];
            #pragma unroll
            for (int i = 0; i < TM; i += 4)
                *(float4*)&ar_[i] = *(const float4*)&As[kk][ty * TM + i];
            #pragma unroll
            for (int j = 0; j < TN; j += 4)
                *(float4*)&br_[j] = *(const float4*)&Bs[kk][tx * TN + j];
            #pragma unroll
            for (int i = 0; i < TM; i++)
                #pragma unroll
                for (int j = 0; j < TN; j++)
                    acc[i][j] = fmaf(ar_[i], br_[j], acc[i][j]);
        }
        __syncthreads();
    }

    float* __restrict__ O = gbuf(OID);
    const float dt6 = dt * (1.0f / 6.0f);

    #pragma unroll
    for (int i = 0; i < TM; i++) {
        const int m = bm + ty * TM + i;
        #pragma unroll
        for (int j = 0; j < TN; j += 4) {
            const int n = bn + tx * TN + j;
            float4 r;
            r.x = acc[i][j + 0] + bias[n + 0];
            r.y = acc[i][j + 1] + bias[n + 1];
            r.z = acc[i][j + 2] + bias[n + 2];
            r.w = acc[i][j + 3] + bias[n + 3];
            if constexpr (EPI == 0) {
                r.x = fast_tanh(r.x); r.y = fast_tanh(r.y);
                r.z = fast_tanh(r.z); r.w = fast_tanh(r.w);
                *(float4*)(O + (size_t)m * N + n) = r;
            } else if constexpr (EPI == 1) {
                *(float4*)(O + (size_t)m * N + n) = r;
            } else {
                const int idx = m * D_ + n;
                float4 y  = *(float4*)&g_Y [idx];
                float4 k1 = *(float4*)&g_K1[idx];
                float4 k2 = *(float4*)&g_K2[idx];
                float4 k3 = *(float4*)&g_K3[idx];
                y.x += dt6 * (k1.x + 2.0f*k2.x + 2.0f*k3.x + r.x);
                y.y += dt6 * (k1.y + 2.0f*k2.y + 2.0f*k3.y + r.y);
                y.z += dt6 * (k1.z + 2.0f*k2.z + 2.0f*k3.z + r.z);
                y.w += dt6 * (k1.w + 2.0f*k2.w + 2.0f*k3.w + r.w);
                *(float4*)&g_Y[idx] = y;
                *(float4*)(dout + ((size_t)m * T_ + (step + 1)) * D_ + n) = y;
            }
        }
    }
}

// t=0 slot: copy first_point into traj[:, 0, :] and into the running state Y
__global__ void init_k(const float* __restrict__ fp, float* __restrict__ out) {
    int i = blockIdx.x * blockDim.x + threadIdx.x;
    if (i < M_ * D_) {
        float v = fp[i];
        g_Y[i] = v;
        int m = i >> 8;          // / 256
        int d = i & 255;
        out[(size_t)m * T_ * D_ + d] = v;
    }
}

// reg_state tail (output buffer is poisoned 0xAA; reference returns zeros)
__global__ void tail_k(float* __restrict__ out, int out_size) {
    int i = PRED + blockIdx.x * blockDim.x + threadIdx.x;
    if (i < out_size) out[i] = 0.0f;
}

extern "C" void kernel_launch(void* const* d_in, const int* in_sizes, int n_in,
                              void* d_out, int out_size)
{
    const float* fp   = (const float*)d_in[0];
    const float* tarr = (const float*)d_in[1];
    const float* W1   = (const float*)d_in[2];
    const float* b1   = (const float*)d_in[3];
    const float* W2   = (const float*)d_in[4];
    const float* b2   = (const float*)d_in[5];
    const float* W3   = (const float*)d_in[6];
    const float* b3   = (const float*)d_in[7];
    float* out = (float*)d_out;
    (void)in_sizes; (void)n_in;

    init_k<<<(M_*D_ + 255)/256, 256>>>(fp, out);
    if (out_size > PRED)
        tail_k<<<(out_size - PRED + 255)/256, 256>>>(out, out_size);

    dim3 blk(256);
    dim3 gH(H_/64, M_/128);   // (16,16) for the two H-wide layers
    dim3 gD(D_/64, M_/64);    // (4,32)  for the D-wide layer 3

    for (int s = 0; s < T_ - 1; s++) {
        // eval 1: f(Y)
        gemm_k<128,64,16,8,4, D_,H_, BUF_Y ,BUF_Y ,BUF_H1,0,0><<<gH,blk>>>(W1,b1,out,tarr,s,0.0f);
        gemm_k<128,64,16,8,4, H_,H_, BUF_H1,BUF_Y ,BUF_H2,0,0><<<gH,blk>>>(W2,b2,out,tarr,s,0.0f);
        gemm_k< 64,64,16,4,4, H_,D_, BUF_H2,BUF_Y ,BUF_K1,0,1><<<gD,blk>>>(W3,b3,out,tarr,s,0.0f);
        // eval 2: f(Y + 0.5 dt K1)
        gemm_k<128,64,16,8,4, D_,H_, BUF_Y ,BUF_K1,BUF_H1,1,0><<<gH,blk>>>(W1,b1,out,tarr,s,0.5f);
        gemm_k<128,64,16,8,4, H_,H_, BUF_H1,BUF_Y ,BUF_H2,0,0><<<gH,blk>>>(W2,b2,out,tarr,s,0.0f);
        gemm_k< 64,64,16,4,4, H_,D_, BUF_H2,BUF_Y ,BUF_K2,0,1><<<gD,blk>>>(W3,b3,out,tarr,s,0.0f);
        // eval 3: f(Y + 0.5 dt K2)
        gemm_k<128,64,16,8,4, D_,H_, BUF_Y ,BUF_K2,BUF_H1,1,0><<<gH,blk>>>(W1,b1,out,tarr,s,0.5f);
        gemm_k<128,64,16,8,4, H_,H_, BUF_H1,BUF_Y ,BUF_H2,0,0><<<gH,blk>>>(W2,b2,out,tarr,s,0.0f);
        gemm_k< 64,64,16,4,4, H_,D_, BUF_H2,BUF_Y ,BUF_K3,0,1><<<gD,blk>>>(W3,b3,out,tarr,s,0.0f);
        // eval 4: f(Y + dt K3), combine fused into layer-3 epilogue
        gemm_k<128,64,16,8,4, D_,H_, BUF_Y ,BUF_K3,BUF_H1,1,0><<<gH,blk>>>(W1,b1,out,tarr,s,1.0f);
        gemm_k<128,64,16,8,4, H_,H_, BUF_H1,BUF_Y ,BUF_H2,0,0><<<gH,blk>>>(W2,b2,out,tarr,s,0.0f);
        gemm_k< 64,64,16,4,4, H_,D_, BUF_H2,BUF_Y ,BUF_K1,0,2><<<gD,blk>>>(W3,b3,out,tarr,s,0.0f);
    }
}

// round 3
// speedup vs baseline: 2.5480x; 2.5480x over previous
#include <cuda_runtime.h>
#include <cuda_bf16.h>
#include <cstdint>
#include <cstddef>

#define S_ 4
#define B_ 512
#define D_ 256
#define H_ 1024
#define T_ 50
#define M_ (S_*B_)          // 2048
#define PRED (M_*T_*D_)

// ---------------- device scratch (no allocation allowed) ----------------
__device__ __nv_bfloat16 g_Ahi[M_*D_],  g_Alo[M_*D_];      // layer-1 input (probe state, split)
__device__ __nv_bfloat16 g_H1hi[M_*H_], g_H1lo[M_*H_];
__device__ __nv_bfloat16 g_H2hi[M_*H_], g_H2lo[M_*H_];
__device__ float g_K1[M_*D_], g_K2[M_*D_], g_K3[M_*D_], g_Y[M_*D_];
// weights transposed to [N,K], split hi/lo bf16
__device__ __nv_bfloat16 g_W1hi[H_*D_], g_W1lo[H_*D_];
__device__ __nv_bfloat16 g_W2hi[H_*H_], g_W2lo[H_*H_];
__device__ __nv_bfloat16 g_W3hi[D_*H_], g_W3lo[D_*H_];

// ---------------- helpers ----------------
__device__ __forceinline__ uint32_t smem_u32(const void* p) {
    uint32_t a;
    asm("{ .reg .u64 t; cvta.to.shared.u64 t, %1; cvt.u32.u64 %0, t; }" : "=r"(a) : "l"(p));
    return a;
}
__device__ __forceinline__ void cp_async16(uint32_t saddr, const void* gaddr) {
    asm volatile("cp.async.cg.shared.global [%0], [%1], 16;" :: "r"(saddr), "l"(gaddr));
}
#define CP_COMMIT() asm volatile("cp.async.commit_group;" ::: "memory")
#define CP_WAIT2()  asm volatile("cp.async.wait_group 2;" ::: "memory")

__device__ __forceinline__ void ldsm_x4(uint32_t* r, uint32_t addr) {
    asm volatile("ldmatrix.sync.aligned.m8n8.x4.shared.b16 {%0,%1,%2,%3}, [%4];"
                 : "=r"(r[0]), "=r"(r[1]), "=r"(r[2]), "=r"(r[3]) : "r"(addr));
}
__device__ __forceinline__ void mma16816(float* c, const uint32_t* a, uint32_t b0, uint32_t b1) {
    asm volatile("mma.sync.aligned.m16n8k16.row.col.f32.bf16.bf16.f32 "
                 "{%0,%1,%2,%3}, {%4,%5,%6,%7}, {%8,%9}, {%0,%1,%2,%3};"
                 : "+f"(c[0]), "+f"(c[1]), "+f"(c[2]), "+f"(c[3])
                 : "r"(a[0]), "r"(a[1]), "r"(a[2]), "r"(a[3]), "r"(b0), "r"(b1));
}

__device__ __forceinline__ float fast_tanh(float x) {
    float t = __expf(2.0f * x);
    return 1.0f - 2.0f / (t + 1.0f);
}
// split pair of floats into bf16x2 hi + bf16x2 lo words
__device__ __forceinline__ void split2(float a, float b, uint32_t& hi, uint32_t& lo) {
    __nv_bfloat16 ha = __float2bfloat16_rn(a), hb = __float2bfloat16_rn(b);
    __nv_bfloat162 ph; ph.x = ha; ph.y = hb;
    hi = *reinterpret_cast<uint32_t*>(&ph);
    __nv_bfloat162 pl = __floats2bfloat162_rn(a - __bfloat162float(ha), b - __bfloat162float(hb));
    lo = *reinterpret_cast<uint32_t*>(&pl);
}

// ---------------- tensor-core (HMMA) GEMM ----------------
// C[M=2048, NFULL] = A[M,KDIM] @ W^T  (W stored [NFULL,KDIM] hi/lo)
// flat chunk list over 3 split terms: term0 Ahi*Whi, term1 Ahi*Wlo, term2 Alo*Whi
// EPI 0: tanh -> split -> Ohi/Olo
// EPI 1: k=C+bias; Kout=k; probe=Y+alpha*dt*k -> split -> Ohi/Olo
// EPI 2: k4=C+bias; y'=Y+dt/6*(K1+2K2+2K3+k4); Y=y'; traj store; split(y') -> Ohi/Olo
template<int BM, int BN, int WM, int WN, int KDIM, int NFULL, int EPI>
__global__ void __launch_bounds__(256)
gemm_mma(const __nv_bfloat16* __restrict__ Ahi, const __nv_bfloat16* __restrict__ Alo,
         const __nv_bfloat16* __restrict__ Whi, const __nv_bfloat16* __restrict__ Wlo,
         const float* __restrict__ bias,
         __nv_bfloat16* __restrict__ Ohi, __nv_bfloat16* __restrict__ Olo,
         float* __restrict__ Kout,
         const float* __restrict__ K1c, const float* __restrict__ K2c, const float* __restrict__ K3c,
         float* __restrict__ Ybuf, float* __restrict__ dout,
         const float* __restrict__ tarr, int step, float alpha)
{
    constexpr int WARPS_M = BM / WM;
    constexpr int KC64    = KDIM / 64;          // 64-elem K chunks per term
    constexpr int NC      = 3 * KC64;           // flat chunk count (3 split terms)
    constexpr int STAGE   = (BM + BN) * 128;    // bytes per pipeline stage
    constexpr int MI = WM / 16, NJ = WN / 8, NJJ = WN / 16;

    extern __shared__ __align__(128) char sm[];
    const uint32_t smb = smem_u32(sm);

    const int tid  = threadIdx.x;
    const int wid  = tid >> 5, lane = tid & 31;
    const int wm   = wid % WARPS_M, wn = wid / WARPS_M;
    const int bm   = blockIdx.y * BM;
    const int bn   = blockIdx.x * BN;

    float acc[MI][NJ][4];
    #pragma unroll
    for (int i = 0; i < MI; i++)
        #pragma unroll
        for (int j = 0; j < NJ; j++)
            #pragma unroll
            for (int q = 0; q < 4; q++) acc[i][j][q] = 0.0f;

    // flat-chunk loader: chunk -> (term, k0)
    auto load_chunk = [&](int c, int slot) {
        const int term = c / KC64;
        const int k0   = (c % KC64) * 64;
        const __nv_bfloat16* __restrict__ As = (term < 2)  ? Ahi : Alo;
        const __nv_bfloat16* __restrict__ Ws = (term == 1) ? Wlo : Whi;
        const uint32_t sb = smb + (uint32_t)slot * STAGE;
        #pragma unroll
        for (int i = tid; i < (BM + BN) * 8; i += 256) {
            const bool isA = i < BM * 8;
            const int  row = (isA ? i : i - BM * 8) >> 3;
            const int  seg = i & 7;
            const __nv_bfloat16* src = isA
                ? As + (size_t)(bm + row) * KDIM + k0 + seg * 8
                : Ws + (size_t)(bn + row) * KDIM + k0 + seg * 8;
            const uint32_t dst = sb + (isA ? 0 : BM * 128)
                               + (uint32_t)row * 128 + (uint32_t)((seg ^ (row & 7)) << 4);
            cp_async16(dst, src);
        }
    };

    // prologue: fill 3 stages
    load_chunk(0, 0); CP_COMMIT();
    load_chunk(1, 1); CP_COMMIT();
    load_chunk(2, 2); CP_COMMIT();

    const int oct = lane >> 3, lr = lane & 7;

    for (int c = 0; c < NC; c++) {
        CP_WAIT2();
        __syncthreads();
        const uint32_t sb = smb + (uint32_t)(c % 3) * STAGE;
        const uint32_t Ab = sb;
        const uint32_t Bb = sb + BM * 128;

        #pragma unroll
        for (int t = 0; t < 4; t++) {
            uint32_t af[MI][4], bf[NJJ][4];
            #pragma unroll
            for (int i = 0; i < MI; i++) {
                const int row = wm * WM + i * 16 + (oct & 1) * 8 + lr;
                const int ks  = t * 2 + (oct >> 1);
                ldsm_x4(af[i], Ab + (uint32_t)row * 128 + (uint32_t)(((ks ^ (row & 7)) << 4)));
            }
            #pragma unroll
            for (int jj = 0; jj < NJJ; jj++) {
                const int row = wn * WN + jj * 16 + (oct >> 1) * 8 + lr;
                const int ks  = t * 2 + (oct & 1);
                ldsm_x4(bf[jj], Bb + (uint32_t)row * 128 + (uint32_t)(((ks ^ (row & 7)) << 4)));
            }
            #pragma unroll
            for (int i = 0; i < MI; i++)
                #pragma unroll
                for (int j = 0; j < NJ; j++)
                    mma16816(acc[i][j], af[i], bf[j >> 1][(j & 1) * 2], bf[j >> 1][(j & 1) * 2 + 1]);
        }
        __syncthreads();
        if (c + 3 < NC) load_chunk(c + 3, c % 3);
        CP_COMMIT();
    }

    // ---------------- fused epilogue ----------------
    float dt = 0.0f;
    if (EPI != 0) dt = tarr[step + 1] - tarr[step];
    const float ad = alpha * dt;
    const float c6 = dt * (1.0f / 6.0f);

    const int r00   = bm + wm * WM + (lane >> 2);
    const int cbase = bn + wn * WN + (lane & 3) * 2;

    #pragma unroll
    for (int i = 0; i < MI; i++) {
        #pragma unroll
        for (int j = 0; j < NJ; j++) {
            const int cc = cbase + j * 8;
            const float2 bs = *(const float2*)&bias[cc];
            const int rows[2] = { r00 + i * 16, r00 + i * 16 + 8 };
            #pragma unroll
            for (int h = 0; h < 2; h++) {
                float v0 = acc[i][j][2*h + 0] + bs.x;
                float v1 = acc[i][j][2*h + 1] + bs.y;
                const size_t idx = (size_t)rows[h] * NFULL + cc;
                if (EPI == 0) {
                    v0 = fast_tanh(v0); v1 = fast_tanh(v1);
                    uint32_t hi, lo; split2(v0, v1, hi, lo);
                    *(uint32_t*)(Ohi + idx) = hi;
                    *(uint32_t*)(Olo + idx) = lo;
                } else if (EPI == 1) {
                    *(float2*)&Kout[idx] = make_float2(v0, v1);
                    const float2 y = *(const float2*)&Ybuf[idx];
                    const float p0 = fmaf(ad, v0, y.x);
                    const float p1 = fmaf(ad, v1, y.y);
                    uint32_t hi, lo; split2(p0, p1, hi, lo);
                    *(uint32_t*)(Ohi + idx) = hi;
                    *(uint32_t*)(Olo + idx) = lo;
                } else {
                    const float2 y  = *(const float2*)&Ybuf[idx];
                    const float2 k1 = *(const float2*)&K1c[idx];
                    const float2 k2 = *(const float2*)&K2c[idx];
                    const float2 k3 = *(const float2*)&K3c[idx];
                    const float y0 = y.x + c6 * (k1.x + 2.0f*k2.x + 2.0f*k3.x + v0);
                    const float y1 = y.y + c6 * (k1.y + 2.0f*k2.y + 2.0f*k3.y + v1);
                    *(float2*)&Ybuf[idx] = make_float2(y0, y1);
                    *(float2*)&dout[((size_t)rows[h] * T_ + step + 1) * NFULL + cc] =
                        make_float2(y0, y1);
                    uint32_t hi, lo; split2(y0, y1, hi, lo);
                    *(uint32_t*)(Ohi + idx) = hi;
                    *(uint32_t*)(Olo + idx) = lo;
                }
            }
        }
    }
}

// ---------------- weight prep: W[K,N] fp32 -> Wt[N,K] bf16 hi/lo ----------------
__global__ void prep_w(const float* __restrict__ W,
                       __nv_bfloat16* __restrict__ Whi, __nv_bfloat16* __restrict__ Wlo,
                       int K, int N)
{
    __shared__ float s[32][33];
    int k0 = blockIdx.y * 32, n0 = blockIdx.x * 32;
    int tx = threadIdx.x, ty = threadIdx.y;   // (32,8)
    #pragma unroll
    for (int r = 0; r < 4; r++)
        s[ty + r*8][tx] = W[(size_t)(k0 + ty + r*8) * N + n0 + tx];
    __syncthreads();
    #pragma unroll
    for (int r = 0; r < 4; r++) {
        int n = n0 + ty + r*8;
        float v = s[tx][ty + r*8];
        __nv_bfloat16 h = __float2bfloat16_rn(v);
        Whi[(size_t)n * K + k0 + tx] = h;
        Wlo[(size_t)n * K + k0 + tx] = __float2bfloat16_rn(v - __bfloat162float(h));
    }
}

__global__ void init_k(const float* __restrict__ fp, float* __restrict__ out) {
    int i = blockIdx.x * blockDim.x + threadIdx.x;
    if (i < M_ * D_) {
        float v = fp[i];
        g_Y[i] = v;
        __nv_bfloat16 h = __float2bfloat16_rn(v);
        g_Ahi[i] = h;
        g_Alo[i] = __float2bfloat16_rn(v - __bfloat162float(h));
        int m = i >> 8, d = i & 255;
        out[(size_t)m * T_ * D_ + d] = v;
    }
}

__global__ void tail_k(float* __restrict__ out, int out_size) {
    int i = PRED + blockIdx.x * blockDim.x + threadIdx.x;
    if (i < out_size) out[i] = 0.0f;
}

// ---------------- host ----------------
template<typename T> static T* sym(const void* s) {
    void* p = nullptr;
    cudaGetSymbolAddress(&p, s);
    return (T*)p;
}

extern "C" void kernel_launch(void* const* d_in, const int* in_sizes, int n_in,
                              void* d_out, int out_size)
{
    const float* fp   = (const float*)d_in[0];
    const float* tarr = (const float*)d_in[1];
    const float* W1   = (const float*)d_in[2];
    const float* b1   = (const float*)d_in[3];
    const float* W2   = (const float*)d_in[4];
    const float* b2   = (const float*)d_in[5];
    const float* W3   = (const float*)d_in[6];
    const float* b3   = (const float*)d_in[7];
    float* out = (float*)d_out;
    (void)in_sizes; (void)n_in;

    __nv_bfloat16 *Ahi = sym<__nv_bfloat16>(g_Ahi), *Alo = sym<__nv_bfloat16>(g_Alo);
    __nv_bfloat16 *H1h = sym<__nv_bfloat16>(g_H1hi), *H1l = sym<__nv_bfloat16>(g_H1lo);
    __nv_bfloat16 *H2h = sym<__nv_bfloat16>(g_H2hi), *H2l = sym<__nv_bfloat16>(g_H2lo);
    __nv_bfloat16 *W1h = sym<__nv_bfloat16>(g_W1hi), *W1l = sym<__nv_bfloat16>(g_W1lo);
    __nv_bfloat16 *W2h = sym<__nv_bfloat16>(g_W2hi), *W2l = sym<__nv_bfloat16>(g_W2lo);
    __nv_bfloat16 *W3h = sym<__nv_bfloat16>(g_W3hi), *W3l = sym<__nv_bfloat16>(g_W3lo);
    float *K1 = sym<float>(g_K1), *K2 = sym<float>(g_K2), *K3 = sym<float>(g_K3);
    float *Y  = sym<float>(g_Y);

    // SMEM: 3 stages of (BM+BN)*128 bytes
    constexpr int SM_H = 3 * (128 + 64) * 128;   // 73728
    constexpr int SM_D = 3 * (64 + 64) * 128;    // 49152
    cudaFuncSetAttribute((const void*)gemm_mma<128,64,32,32, D_,H_,0>,
                         cudaFuncAttributeMaxDynamicSharedMemorySize, SM_H);
    cudaFuncSetAttribute((const void*)gemm_mma<128,64,32,32, H_,H_,0>,
                         cudaFuncAttributeMaxDynamicSharedMemorySize, SM_H);
    cudaFuncSetAttribute((const void*)gemm_mma<64,64,32,16, H_,D_,1>,
                         cudaFuncAttributeMaxDynamicSharedMemorySize, SM_D);
    cudaFuncSetAttribute((const void*)gemm_mma<64,64,32,16, H_,D_,2>,
                         cudaFuncAttributeMaxDynamicSharedMemorySize, SM_D);

    prep_w<<<dim3(H_/32, D_/32), dim3(32,8)>>>(W1, W1h, W1l, D_, H_);
    prep_w<<<dim3(H_/32, H_/32), dim3(32,8)>>>(W2, W2h, W2l, H_, H_);
    prep_w<<<dim3(D_/32, H_/32), dim3(32,8)>>>(W3, W3h, W3l, H_, D_);

    init_k<<<(M_*D_ + 255)/256, 256>>>(fp, out);
    if (out_size > PRED)
        tail_k<<<(out_size - PRED + 255)/256, 256>>>(out, out_size);

    dim3 blk(256);
    dim3 gH(H_/64, M_/128);   // (16,16) = 256 CTAs
    dim3 gD(D_/64, M_/64);    // (4,32)  = 128 CTAs

    for (int s = 0; s < T_ - 1; s++) {
        // eval 1: f(Y)
        gemm_mma<128,64,32,32, D_,H_,0><<<gH, blk, SM_H>>>(Ahi, Alo, W1h, W1l, b1, H1h, H1l,
            nullptr, nullptr, nullptr, nullptr, nullptr, nullptr, tarr, s, 0.f);
        gemm_mma<128,64,32,32, H_,H_,0><<<gH, blk, SM_H>>>(H1h, H1l, W2h, W2l, b2, H2h, H2l,
            nullptr, nullptr, nullptr, nullptr, nullptr, nullptr, tarr, s, 0.f);
        gemm_mma<64,64,32,16, H_,D_,1><<<gD, blk, SM_D>>>(H2h, H2l, W3h, W3l, b3, Ahi, Alo,
            K1, nullptr, nullptr, nullptr, Y, nullptr, tarr, s, 0.5f);
        // eval 2
        gemm_mma<128,64,32,32, D_,H_,0><<<gH, blk, SM_H>>>(Ahi, Alo, W1h, W1l, b1, H1h, H1l,
            nullptr, nullptr, nullptr, nullptr, nullptr, nullptr, tarr, s, 0.f);
        gemm_mma<128,64,32,32, H_,H_,0><<<gH, blk, SM_H>>>(H1h, H1l, W2h, W2l, b2, H2h, H2l,
            nullptr, nullptr, nullptr, nullptr, nullptr, nullptr, tarr, s, 0.f);
        gemm_mma<64,64,32,16, H_,D_,1><<<gD, blk, SM_D>>>(H2h, H2l, W3h, W3l, b3, Ahi, Alo,
            K2, nullptr, nullptr, nullptr, Y, nullptr, tarr, s, 0.5f);
        // eval 3
        gemm_mma<128,64,32,32, D_,H_,0><<<gH, blk, SM_H>>>(Ahi, Alo, W1h, W1l, b1, H1h, H1l,
            nullptr, nullptr, nullptr, nullptr, nullptr, nullptr, tarr, s, 0.f);
        gemm_mma<128,64,32,32, H_,H_,0><<<gH, blk, SM_H>>>(H1h, H1l, W2h, W2l, b2, H2h, H2l,
            nullptr, nullptr, nullptr, nullptr, nullptr, nullptr, tarr, s, 0.f);
        gemm_mma<64,64,32,16, H_,D_,1><<<gD, blk, SM_D>>>(H2h, H2l, W3h, W3l, b3, Ahi, Alo,
            K3, nullptr, nullptr, nullptr, Y, nullptr, tarr, s, 1.0f);
        // eval 4 + RK4 combine fused
        gemm_mma<128,64,32,32, D_,H_,0><<<gH, blk, SM_H>>>(Ahi, Alo, W1h, W1l, b1, H1h, H1l,
            nullptr, nullptr, nullptr, nullptr, nullptr, nullptr, tarr, s, 0.f);
        gemm_mma<128,64,32,32, H_,H_,0><<<gH, blk, SM_H>>>(H1h, H1l, W2h, W2l, b2, H2h, H2l,
            nullptr, nullptr, nullptr, nullptr, nullptr, nullptr, tarr, s, 0.f);
        gemm_mma<64,64,32,16, H_,D_,2><<<gD, blk, SM_D>>>(H2h, H2l, W3h, W3l, b3, Ahi, Alo,
            nullptr, K1, K2, K3, Y, out, tarr, s, 0.f);
    }
}

// round 4
// speedup vs baseline: 2.6120x; 1.0251x over previous
#include <cuda_runtime.h>
#include <cuda_bf16.h>
#include <cstdint>
#include <cstddef>

#define S_ 4
#define B_ 512
#define D_ 256
#define H_ 1024
#define T_ 50
#define M_ (S_*B_)          // 2048
#define PRED (M_*T_*D_)

// ---------------- device scratch (no allocation allowed) ----------------
__device__ __nv_bfloat16 g_Ahi[M_*D_],  g_Alo[M_*D_];      // layer-1 input (probe state, split)
__device__ __nv_bfloat16 g_H1hi[M_*H_], g_H1lo[M_*H_];
__device__ __nv_bfloat16 g_H2hi[M_*H_], g_H2lo[M_*H_];
__device__ float g_K1[M_*D_], g_K2[M_*D_], g_K3[M_*D_], g_Y[M_*D_];
// weights transposed to [N,K], split hi/lo bf16
__device__ __nv_bfloat16 g_W1hi[H_*D_], g_W1lo[H_*D_];
__device__ __nv_bfloat16 g_W2hi[H_*H_], g_W2lo[H_*H_];
__device__ __nv_bfloat16 g_W3hi[D_*H_], g_W3lo[D_*H_];

// ---------------- helpers ----------------
__device__ __forceinline__ uint32_t smem_u32(const void* p) {
    uint32_t a;
    asm("{ .reg .u64 t; cvta.to.shared.u64 t, %1; cvt.u32.u64 %0, t; }" : "=r"(a) : "l"(p));
    return a;
}
__device__ __forceinline__ void cp_async16(uint32_t saddr, const void* gaddr) {
    asm volatile("cp.async.cg.shared.global [%0], [%1], 16;" :: "r"(saddr), "l"(gaddr));
}
#define CP_COMMIT() asm volatile("cp.async.commit_group;" ::: "memory")
#define CP_WAIT2()  asm volatile("cp.async.wait_group 2;" ::: "memory")

__device__ __forceinline__ void ldsm_x4(uint32_t* r, uint32_t addr) {
    asm volatile("ldmatrix.sync.aligned.m8n8.x4.shared.b16 {%0,%1,%2,%3}, [%4];"
                 : "=r"(r[0]), "=r"(r[1]), "=r"(r[2]), "=r"(r[3]) : "r"(addr));
}
__device__ __forceinline__ void mma16816(float* c, const uint32_t* a, uint32_t b0, uint32_t b1) {
    asm volatile("mma.sync.aligned.m16n8k16.row.col.f32.bf16.bf16.f32 "
                 "{%0,%1,%2,%3}, {%4,%5,%6,%7}, {%8,%9}, {%0,%1,%2,%3};"
                 : "+f"(c[0]), "+f"(c[1]), "+f"(c[2]), "+f"(c[3])
                 : "r"(a[0]), "r"(a[1]), "r"(a[2]), "r"(a[3]), "r"(b0), "r"(b1));
}

__device__ __forceinline__ float fast_tanh(float x) {
    float t = __expf(2.0f * x);
    return 1.0f - 2.0f / (t + 1.0f);
}
// split pair of floats into bf16x2 hi + bf16x2 lo words
__device__ __forceinline__ void split2(float a, float b, uint32_t& hi, uint32_t& lo) {
    __nv_bfloat16 ha = __float2bfloat16_rn(a), hb = __float2bfloat16_rn(b);
    __nv_bfloat162 ph; ph.x = ha; ph.y = hb;
    hi = *reinterpret_cast<uint32_t*>(&ph);
    __nv_bfloat162 pl = __floats2bfloat162_rn(a - __bfloat162float(ha), b - __bfloat162float(hb));
    lo = *reinterpret_cast<uint32_t*>(&pl);
}

// ---------------- tensor-core (HMMA) GEMM ----------------
// C[M=2048, NFULL] = A[M,KDIM] @ W^T  (W stored [NFULL,KDIM] hi/lo)
// flat chunk list over 3 split terms: term0 Ahi*Whi, term1 Ahi*Wlo, term2 Alo*Whi
// 4-stage cp.async pipeline, ONE __syncthreads per chunk.
// EPI 0: tanh -> split -> Ohi/Olo
// EPI 1: k=C+bias; Kout=k; probe=Y+alpha*dt*k -> split -> Ohi/Olo
// EPI 2: k4=C+bias; y'=Y+dt/6*(K1+2K2+2K3+k4); Y=y'; traj store; split(y') -> Ohi/Olo
template<int BM, int BN, int WM, int WN, int KDIM, int NFULL, int EPI>
__global__ void __launch_bounds__(256)
gemm_mma(const __nv_bfloat16* __restrict__ Ahi, const __nv_bfloat16* __restrict__ Alo,
         const __nv_bfloat16* __restrict__ Whi, const __nv_bfloat16* __restrict__ Wlo,
         const float* __restrict__ bias,
         __nv_bfloat16* __restrict__ Ohi, __nv_bfloat16* __restrict__ Olo,
         float* __restrict__ Kout,
         const float* __restrict__ K1c, const float* __restrict__ K2c, const float* __restrict__ K3c,
         float* __restrict__ Ybuf, float* __restrict__ dout,
         const float* __restrict__ tarr, int step, float alpha)
{
    constexpr int WARPS_M = BM / WM;
    constexpr int KC64    = KDIM / 64;          // 64-elem K chunks per term
    constexpr int NC      = 3 * KC64;           // flat chunk count (3 split terms)
    constexpr int STAGE   = (BM + BN) * 128;    // bytes per pipeline stage
    constexpr int MI = WM / 16, NJ = WN / 8, NJJ = WN / 16;

    extern __shared__ __align__(128) char sm[];
    const uint32_t smb = smem_u32(sm);

    const int tid  = threadIdx.x;
    const int wid  = tid >> 5, lane = tid & 31;
    const int wm   = wid % WARPS_M, wn = wid / WARPS_M;
    const int bm   = blockIdx.y * BM;
    const int bn   = blockIdx.x * BN;

    float acc[MI][NJ][4];
    #pragma unroll
    for (int i = 0; i < MI; i++)
        #pragma unroll
        for (int j = 0; j < NJ; j++)
            #pragma unroll
            for (int q = 0; q < 4; q++) acc[i][j][q] = 0.0f;

    // flat-chunk loader: chunk -> (term, k0)
    auto load_chunk = [&](int c, int slot) {
        const int term = c / KC64;
        const int k0   = (c % KC64) * 64;
        const __nv_bfloat16* __restrict__ As = (term < 2)  ? Ahi : Alo;
        const __nv_bfloat16* __restrict__ Ws = (term == 1) ? Wlo : Whi;
        const uint32_t sb = smb + (uint32_t)slot * STAGE;
        #pragma unroll
        for (int i = tid; i < (BM + BN) * 8; i += 256) {
            const bool isA = i < BM * 8;
            const int  row = (isA ? i : i - BM * 8) >> 3;
            const int  seg = i & 7;
            const __nv_bfloat16* src = isA
                ? As + (size_t)(bm + row) * KDIM + k0 + seg * 8
                : Ws + (size_t)(bn + row) * KDIM + k0 + seg * 8;
            const uint32_t dst = sb + (isA ? 0 : BM * 128)
                               + (uint32_t)row * 128 + (uint32_t)((seg ^ (row & 7)) << 4);
            cp_async16(dst, src);
        }
    };

    // prologue: fill 3 of 4 stages
    load_chunk(0, 0); CP_COMMIT();
    load_chunk(1, 1); CP_COMMIT();
    load_chunk(2, 2); CP_COMMIT();

    const int oct = lane >> 3, lr = lane & 7;

    for (int c = 0; c < NC; c++) {
        CP_WAIT2();            // stage c data ready
        __syncthreads();       // all warps also done reading stage (c-1)&3
        if (c + 3 < NC) load_chunk(c + 3, (c + 3) & 3);   // overwrite (c-1)&3 — safe post-sync
        CP_COMMIT();

        const uint32_t sb = smb + (uint32_t)(c & 3) * STAGE;
        const uint32_t Ab = sb;
        const uint32_t Bb = sb + BM * 128;

        #pragma unroll
        for (int t = 0; t < 4; t++) {
            uint32_t af[MI][4], bf[NJJ][4];
            #pragma unroll
            for (int i = 0; i < MI; i++) {
                const int row = wm * WM + i * 16 + (oct & 1) * 8 + lr;
                const int ks  = t * 2 + (oct >> 1);
                ldsm_x4(af[i], Ab + (uint32_t)row * 128 + (uint32_t)(((ks ^ (row & 7)) << 4)));
            }
            #pragma unroll
            for (int jj = 0; jj < NJJ; jj++) {
                const int row = wn * WN + jj * 16 + (oct >> 1) * 8 + lr;
                const int ks  = t * 2 + (oct & 1);
                ldsm_x4(bf[jj], Bb + (uint32_t)row * 128 + (uint32_t)(((ks ^ (row & 7)) << 4)));
            }
            #pragma unroll
            for (int i = 0; i < MI; i++)
                #pragma unroll
                for (int j = 0; j < NJ; j++)
                    mma16816(acc[i][j], af[i], bf[j >> 1][(j & 1) * 2], bf[j >> 1][(j & 1) * 2 + 1]);
        }
    }

    // ---------------- fused epilogue ----------------
    float dt = 0.0f;
    if (EPI != 0) dt = tarr[step + 1] - tarr[step];
    const float ad = alpha * dt;
    const float c6 = dt * (1.0f / 6.0f);

    const int r00   = bm + wm * WM + (lane >> 2);
    const int cbase = bn + wn * WN + (lane & 3) * 2;

    #pragma unroll
    for (int i = 0; i < MI; i++) {
        #pragma unroll
        for (int j = 0; j < NJ; j++) {
            const int cc = cbase + j * 8;
            const float2 bs = *(const float2*)&bias[cc];
            const int rows[2] = { r00 + i * 16, r00 + i * 16 + 8 };
            #pragma unroll
            for (int h = 0; h < 2; h++) {
                float v0 = acc[i][j][2*h + 0] + bs.x;
                float v1 = acc[i][j][2*h + 1] + bs.y;
                const size_t idx = (size_t)rows[h] * NFULL + cc;
                if (EPI == 0) {
                    v0 = fast_tanh(v0); v1 = fast_tanh(v1);
                    uint32_t hi, lo; split2(v0, v1, hi, lo);
                    *(uint32_t*)(Ohi + idx) = hi;
                    *(uint32_t*)(Olo + idx) = lo;
                } else if (EPI == 1) {
                    *(float2*)&Kout[idx] = make_float2(v0, v1);
                    const float2 y = *(const float2*)&Ybuf[idx];
                    const float p0 = fmaf(ad, v0, y.x);
                    const float p1 = fmaf(ad, v1, y.y);
                    uint32_t hi, lo; split2(p0, p1, hi, lo);
                    *(uint32_t*)(Ohi + idx) = hi;
                    *(uint32_t*)(Olo + idx) = lo;
                } else {
                    const float2 y  = *(const float2*)&Ybuf[idx];
                    const float2 k1 = *(const float2*)&K1c[idx];
                    const float2 k2 = *(const float2*)&K2c[idx];
                    const float2 k3 = *(const float2*)&K3c[idx];
                    const float y0 = y.x + c6 * (k1.x + 2.0f*k2.x + 2.0f*k3.x + v0);
                    const float y1 = y.y + c6 * (k1.y + 2.0f*k2.y + 2.0f*k3.y + v1);
                    *(float2*)&Ybuf[idx] = make_float2(y0, y1);
                    *(float2*)&dout[((size_t)rows[h] * T_ + step + 1) * NFULL + cc] =
                        make_float2(y0, y1);
                    uint32_t hi, lo; split2(y0, y1, hi, lo);
                    *(uint32_t*)(Ohi + idx) = hi;
                    *(uint32_t*)(Olo + idx) = lo;
                }
            }
        }
    }
}

// ---------------- weight prep: W[K,N] fp32 -> Wt[N,K] bf16 hi/lo ----------------
__global__ void prep_w(const float* __restrict__ W,
                       __nv_bfloat16* __restrict__ Whi, __nv_bfloat16* __restrict__ Wlo,
                       int K, int N)
{
    __shared__ float s[32][33];
    int k0 = blockIdx.y * 32, n0 = blockIdx.x * 32;
    int tx = threadIdx.x, ty = threadIdx.y;   // (32,8)
    #pragma unroll
    for (int r = 0; r < 4; r++)
        s[ty + r*8][tx] = W[(size_t)(k0 + ty + r*8) * N + n0 + tx];
    __syncthreads();
    #pragma unroll
    for (int r = 0; r < 4; r++) {
        int n = n0 + ty + r*8;
        float v = s[tx][ty + r*8];
        __nv_bfloat16 h = __float2bfloat16_rn(v);
        Whi[(size_t)n * K + k0 + tx] = h;
        Wlo[(size_t)n * K + k0 + tx] = __float2bfloat16_rn(v - __bfloat162float(h));
    }
}

__global__ void init_k(const float* __restrict__ fp, float* __restrict__ out) {
    int i = blockIdx.x * blockDim.x + threadIdx.x;
    if (i < M_ * D_) {
        float v = fp[i];
        g_Y[i] = v;
        __nv_bfloat16 h = __float2bfloat16_rn(v);
        g_Ahi[i] = h;
        g_Alo[i] = __float2bfloat16_rn(v - __bfloat162float(h));
        int m = i >> 8, d = i & 255;
        out[(size_t)m * T_ * D_ + d] = v;
    }
}

__global__ void tail_k(float* __restrict__ out, int out_size) {
    int i = PRED + blockIdx.x * blockDim.x + threadIdx.x;
    if (i < out_size) out[i] = 0.0f;
}

// ---------------- host ----------------
template<typename T> static T* sym(const void* s) {
    void* p = nullptr;
    cudaGetSymbolAddress(&p, s);
    return (T*)p;
}

extern "C" void kernel_launch(void* const* d_in, const int* in_sizes, int n_in,
                              void* d_out, int out_size)
{
    const float* fp   = (const float*)d_in[0];
    const float* tarr = (const float*)d_in[1];
    const float* W1   = (const float*)d_in[2];
    const float* b1   = (const float*)d_in[3];
    const float* W2   = (const float*)d_in[4];
    const float* b2   = (const float*)d_in[5];
    const float* W3   = (const float*)d_in[6];
    const float* b3   = (const float*)d_in[7];
    float* out = (float*)d_out;
    (void)in_sizes; (void)n_in;

    __nv_bfloat16 *Ahi = sym<__nv_bfloat16>(g_Ahi), *Alo = sym<__nv_bfloat16>(g_Alo);
    __nv_bfloat16 *H1h = sym<__nv_bfloat16>(g_H1hi), *H1l = sym<__nv_bfloat16>(g_H1lo);
    __nv_bfloat16 *H2h = sym<__nv_bfloat16>(g_H2hi), *H2l = sym<__nv_bfloat16>(g_H2lo);
    __nv_bfloat16 *W1h = sym<__nv_bfloat16>(g_W1hi), *W1l = sym<__nv_bfloat16>(g_W1lo);
    __nv_bfloat16 *W2h = sym<__nv_bfloat16>(g_W2hi), *W2l = sym<__nv_bfloat16>(g_W2lo);
    __nv_bfloat16 *W3h = sym<__nv_bfloat16>(g_W3hi), *W3l = sym<__nv_bfloat16>(g_W3lo);
    float *K1 = sym<float>(g_K1), *K2 = sym<float>(g_K2), *K3 = sym<float>(g_K3);
    float *Y  = sym<float>(g_Y);

    // SMEM: 4 stages of (BM+BN)*128 bytes
    constexpr int SM_H = 4 * (128 + 128) * 128;  // 131072 (H layers, 128x128 tiles)
    constexpr int SM_D = 4 * (64 + 64) * 128;    //  65536 (L3, 64x64 tiles)
    cudaFuncSetAttribute((const void*)gemm_mma<128,128,32,64, D_,H_,0>,
                         cudaFuncAttributeMaxDynamicSharedMemorySize, SM_H);
    cudaFuncSetAttribute((const void*)gemm_mma<128,128,32,64, H_,H_,0>,
                         cudaFuncAttributeMaxDynamicSharedMemorySize, SM_H);
    cudaFuncSetAttribute((const void*)gemm_mma<64,64,32,16, H_,D_,1>,
                         cudaFuncAttributeMaxDynamicSharedMemorySize, SM_D);
    cudaFuncSetAttribute((const void*)gemm_mma<64,64,32,16, H_,D_,2>,
                         cudaFuncAttributeMaxDynamicSharedMemorySize, SM_D);

    prep_w<<<dim3(H_/32, D_/32), dim3(32,8)>>>(W1, W1h, W1l, D_, H_);
    prep_w<<<dim3(H_/32, H_/32), dim3(32,8)>>>(W2, W2h, W2l, H_, H_);
    prep_w<<<dim3(D_/32, H_/32), dim3(32,8)>>>(W3, W3h, W3l, H_, D_);

    init_k<<<(M_*D_ + 255)/256, 256>>>(fp, out);
    if (out_size > PRED)
        tail_k<<<(out_size - PRED + 255)/256, 256>>>(out, out_size);

    dim3 blk(256);
    dim3 gH(H_/128, M_/128);  // (8,16) = 128 CTAs — single wave
    dim3 gD(D_/64,  M_/64);   // (4,32) = 128 CTAs

    for (int s = 0; s < T_ - 1; s++) {
        // eval 1: f(Y)
        gemm_mma<128,128,32,64, D_,H_,0><<<gH, blk, SM_H>>>(Ahi, Alo, W1h, W1l, b1, H1h, H1l,
            nullptr, nullptr, nullptr, nullptr, nullptr, nullptr, tarr, s, 0.f);
        gemm_mma<128,128,32,64, H_,H_,0><<<gH, blk, SM_H>>>(H1h, H1l, W2h, W2l, b2, H2h, H2l,
            nullptr, nullptr, nullptr, nullptr, nullptr, nullptr, tarr, s, 0.f);
        gemm_mma<64,64,32,16, H_,D_,1><<<gD, blk, SM_D>>>(H2h, H2l, W3h, W3l, b3, Ahi, Alo,
            K1, nullptr, nullptr, nullptr, Y, nullptr, tarr, s, 0.5f);
        // eval 2
        gemm_mma<128,128,32,64, D_,H_,0><<<gH, blk, SM_H>>>(Ahi, Alo, W1h, W1l, b1, H1h, H1l,
            nullptr, nullptr, nullptr, nullptr, nullptr, nullptr, tarr, s, 0.f);
        gemm_mma<128,128,32,64, H_,H_,0><<<gH, blk, SM_H>>>(H1h, H1l, W2h, W2l, b2, H2h, H2l,
            nullptr, nullptr, nullptr, nullptr, nullptr, nullptr, tarr, s, 0.f);
        gemm_mma<64,64,32,16, H_,D_,1><<<gD, blk, SM_D>>>(H2h, H2l, W3h, W3l, b3, Ahi, Alo,
            K2, nullptr, nullptr, nullptr, Y, nullptr, tarr, s, 0.5f);
        // eval 3
        gemm_mma<128,128,32,64, D_,H_,0><<<gH, blk, SM_H>>>(Ahi, Alo, W1h, W1l, b1, H1h, H1l,
            nullptr, nullptr, nullptr, nullptr, nullptr, nullptr, tarr, s, 0.f);
        gemm_mma<128,128,32,64, H_,H_,0><<<gH, blk, SM_H>>>(H1h, H1l, W2h, W2l, b2, H2h, H2l,
            nullptr, nullptr, nullptr, nullptr, nullptr, nullptr, tarr, s, 0.f);
        gemm_mma<64,64,32,16, H_,D_,1><<<gD, blk, SM_D>>>(H2h, H2l, W3h, W3l, b3, Ahi, Alo,
            K3, nullptr, nullptr, nullptr, Y, nullptr, tarr, s, 1.0f);
        // eval 4 + RK4 combine fused
        gemm_mma<128,128,32,64, D_,H_,0><<<gH, blk, SM_H>>>(Ahi, Alo, W1h, W1l, b1, H1h, H1l,
            nullptr, nullptr, nullptr, nullptr, nullptr, nullptr, tarr, s, 0.f);
        gemm_mma<128,128,32,64, H_,H_,0><<<gH, blk, SM_H>>>(H1h, H1l, W2h, W2l, b2, H2h, H2l,
            nullptr, nullptr, nullptr, nullptr, nullptr, nullptr, tarr, s, 0.f);
        gemm_mma<64,64,32,16, H_,D_,2><<<gD, blk, SM_D>>>(H2h, H2l, W3h, W3l, b3, Ahi, Alo,
            nullptr, K1, K2, K3, Y, out, tarr, s, 0.f);
    }
}